// round 8
// baseline (speedup 1.0000x reference)
#include <cuda_runtime.h>
#include <cuda_fp16.h>
#include <cstdint>
#include <math.h>

// Problem shape (fixed): B=8, T=2048, C=1024
constexpr int kB = 8;
constexpr int kT = 2048;
constexpr int kC = 1024;
constexpr int kM = kB * kT;                 // 16384 rows
constexpr size_t kMC = (size_t)kM * kC;
constexpr size_t kCC = (size_t)kC * kC;

// WKV blocked-scan config
constexpr int kSeg    = 16;
constexpr int kSegLen = kT / kSeg;          // 128

// ---------------------------------------------------------------------------
// Scratch (__device__ globals; no allocations allowed)
// ---------------------------------------------------------------------------
__device__ __half g_a[3][kMC];     // mixed inputs (k,v,r) in fp16
__device__ __half g_wh[3][kCC];    // wk,wv,wr hi
__device__ __half g_wkl[kCC];      // wk lo
__device__ __half g_woh[kCC];
__device__ __half g_wol[kCC];
__device__ float  g_kvr[3][kMC];   // key, value, sigmoid(r)
__device__ __half g_rw[kMC];       // rwkv in fp16
__device__ float g_segN[(size_t)kB * kSeg * kC];
__device__ float g_segD[(size_t)kB * kSeg * kC];
__device__ float g_segM[(size_t)kB * kSeg * kC];

// ---------------------------------------------------------------------------
// PTX helpers
// ---------------------------------------------------------------------------
__device__ __forceinline__ uint32_t smem_u32(const void* p) {
    uint32_t a;
    asm("{ .reg .u64 t; cvta.to.shared.u64 t, %1; cvt.u32.u64 %0, t; }"
        : "=r"(a) : "l"(p));
    return a;
}
__device__ __forceinline__ void cp_async16(uint32_t saddr, const void* gptr) {
    asm volatile("cp.async.ca.shared.global [%0], [%1], 16;"
                 :: "r"(saddr), "l"(gptr));
}
__device__ __forceinline__ void cp_commit() {
    asm volatile("cp.async.commit_group;");
}
template <int N>
__device__ __forceinline__ void cp_wait() {
    asm volatile("cp.async.wait_group %0;" :: "n"(N));
}
__device__ __forceinline__ void ldsm_x4(uint32_t* r, uint32_t addr) {
    asm volatile("ldmatrix.sync.aligned.m8n8.x4.shared.b16 {%0,%1,%2,%3}, [%4];"
                 : "=r"(r[0]), "=r"(r[1]), "=r"(r[2]), "=r"(r[3]) : "r"(addr));
}
__device__ __forceinline__ void mma16816(float* d, const uint32_t* a, const uint32_t* b) {
    asm volatile("mma.sync.aligned.m16n8k16.row.col.f32.f16.f16.f32 "
                 "{%0,%1,%2,%3}, {%4,%5,%6,%7}, {%8,%9}, {%0,%1,%2,%3};"
                 : "+f"(d[0]), "+f"(d[1]), "+f"(d[2]), "+f"(d[3])
                 : "r"(a[0]), "r"(a[1]), "r"(a[2]), "r"(a[3]), "r"(b[0]), "r"(b[1]));
}

// ---------------------------------------------------------------------------
// fp16 helpers
// ---------------------------------------------------------------------------
__device__ __forceinline__ void split1(float a, __half& h, __half& l) {
    h = __float2half_rn(a);
    l = __float2half_rn(a - __half2float(h));
}
__device__ __forceinline__ void h4_store(const float* a, __half* d, size_t off) {
    unsigned short u[4];
#pragma unroll
    for (int i = 0; i < 4; i++) u[i] = __half_as_ushort(__float2half_rn(a[i]));
    *(uint2*)(d + off) = make_uint2((uint32_t)u[0] | ((uint32_t)u[1] << 16),
                                    (uint32_t)u[2] | ((uint32_t)u[3] << 16));
}
__device__ __forceinline__ void split4_store(const float* a, __half* dh, __half* dl,
                                             size_t off) {
    unsigned short uh[4], ul[4];
#pragma unroll
    for (int i = 0; i < 4; i++) {
        __half h, l;
        split1(a[i], h, l);
        uh[i] = __half_as_ushort(h);
        ul[i] = __half_as_ushort(l);
    }
    *(uint2*)(dh + off) = make_uint2((uint32_t)uh[0] | ((uint32_t)uh[1] << 16),
                                     (uint32_t)uh[2] | ((uint32_t)uh[3] << 16));
    *(uint2*)(dl + off) = make_uint2((uint32_t)ul[0] | ((uint32_t)ul[1] << 16),
                                     (uint32_t)ul[2] | ((uint32_t)ul[3] << 16));
}

// ---------------------------------------------------------------------------
// prep kernels
// ---------------------------------------------------------------------------
__global__ void prep_w_kernel(const float* __restrict__ wk, const float* __restrict__ wv,
                              const float* __restrict__ wr, const float* __restrict__ wo) {
    const int mat = blockIdx.y;
    const int row = blockIdx.x;
    const int c4  = threadIdx.x;
    const size_t off = (size_t)row * kC + c4 * 4;
    if (mat == 0) {
        float4 v = ((const float4*)(wk + (size_t)row * kC))[c4];
        split4_store((const float*)&v, g_wh[0], g_wkl, off);
    } else if (mat == 1) {
        float4 v = ((const float4*)(wv + (size_t)row * kC))[c4];
        h4_store((const float*)&v, g_wh[1], off);
    } else if (mat == 2) {
        float4 v = ((const float4*)(wr + (size_t)row * kC))[c4];
        h4_store((const float*)&v, g_wh[2], off);
    } else {
        float4 v = ((const float4*)(wo + (size_t)row * kC))[c4];
        split4_store((const float*)&v, g_woh, g_wol, off);
    }
}

__global__ void prep_a_kernel(const float* __restrict__ x,
                              const float* __restrict__ mk,
                              const float* __restrict__ mv,
                              const float* __restrict__ mr) {
    const int row = blockIdx.x;
    const int c4  = threadIdx.x;
    const float4 xv = ((const float4*)(x + (size_t)row * kC))[c4];
    float4 pv = make_float4(0.f, 0.f, 0.f, 0.f);
    if ((row & (kT - 1)) != 0)
        pv = ((const float4*)(x + (size_t)(row - 1) * kC))[c4];
    const float4 m0 = ((const float4*)mk)[c4];
    const float4 m1 = ((const float4*)mv)[c4];
    const float4 m2 = ((const float4*)mr)[c4];
    const float* xe = (const float*)&xv;
    const float* pe = (const float*)&pv;
    const float* me[3] = {(const float*)&m0, (const float*)&m1, (const float*)&m2};
    const size_t off = (size_t)row * kC + c4 * 4;
#pragma unroll
    for (int s = 0; s < 3; s++) {
        float a[4];
#pragma unroll
        for (int i = 0; i < 4; i++)
            a[i] = fmaf(me[s][i], xe[i] - pe[i], pe[i]);
        h4_store(a, g_a[s], off);
    }
}

// ---------------------------------------------------------------------------
// fp16 warp-MMA GEMM: out[m,n] = sum_k A[m,k]*(Bh[+Bl])[n,k]
// CTA tile 128x128, K-chunk 64, 8 warps (warp tile 32x64), cp.async dbl-buffer
// ---------------------------------------------------------------------------
constexpr int kStrideB16 = 72;               // padded smem row stride (b16)
constexpr int kRowBytes  = kStrideB16 * 2;   // 144
constexpr int kTileBytes = 128 * kRowBytes;  // 18432
constexpr int kStageBytes = 3 * kTileBytes;  // 55296 (A, Bh, [Bl]) - unified
constexpr int kSmemBytes  = 2 * kStageBytes; // 110592
constexpr int OFF_A  = 0;
constexpr int OFF_BH = kTileBytes;
constexpr int OFF_BL = 2 * kTileBytes;

template <bool SPLIT>
__device__ __forceinline__ void load_chunk(uint32_t sb, int stage, int tid,
                                           const __half* A, const __half* Bh,
                                           const __half* Bl,
                                           int m0, int n0, int k0) {
    constexpr int nT = SPLIT ? 3 : 2;
    const uint32_t st = sb + stage * kStageBytes;
    const __half* srcs[3] = {A, Bh, Bl};
    const int bases[3] = {m0, n0, n0};
    const uint32_t offs[3] = {OFF_A, OFF_BH, OFF_BL};
#pragma unroll
    for (int t = 0; t < nT; t++) {
#pragma unroll
        for (int rep = 0; rep < 4; rep++) {
            const int j = tid + rep * 256;         // 0..1023
            const int row = j >> 3;
            const int seg = j & 7;
            const __half* g = srcs[t] + (size_t)(bases[t] + row) * kC + k0 + seg * 8;
            cp_async16(st + offs[t] + row * kRowBytes + seg * 16, g);
        }
    }
}

template <bool SPLIT>
__device__ __forceinline__ void gemm_body(const __half* __restrict__ A,
                                          const __half* __restrict__ Bh,
                                          const __half* __restrict__ Bl,
                                          float* __restrict__ out,
                                          int epi_sigmoid) {
    extern __shared__ char smem[];
    const uint32_t sb = smem_u32(smem);
    const int tid  = threadIdx.x;
    const int wid  = tid >> 5;
    const int lane = tid & 31;
    const int wm   = wid & 3;
    const int wn   = wid >> 2;

    const int m0 = blockIdx.y * 128;
    const int n0 = blockIdx.x * 128;

    float acc[2][8][4];
#pragma unroll
    for (int mt = 0; mt < 2; mt++)
#pragma unroll
        for (int nt = 0; nt < 8; nt++)
#pragma unroll
            for (int i = 0; i < 4; i++) acc[mt][nt][i] = 0.f;

    const uint32_t aRowOff = (uint32_t)((wm * 32 + (lane & 15)) * kRowBytes + (lane >> 4) * 16);
    const uint32_t bRowOff = (uint32_t)((wn * 64 + (lane & 7) + ((lane & 16) >> 1)) * kRowBytes
                                        + ((lane >> 3) & 1) * 16);

    load_chunk<SPLIT>(sb, 0, tid, A, Bh, Bl, m0, n0, 0);
    cp_commit();

    const int nChunks = kC / 64;   // 16
    for (int c = 0; c < nChunks; c++) {
        if (c + 1 < nChunks) {
            load_chunk<SPLIT>(sb, (c + 1) & 1, tid, A, Bh, Bl, m0, n0, (c + 1) * 64);
            cp_commit();
            cp_wait<1>();
        } else {
            cp_wait<0>();
        }
        __syncthreads();

        const uint32_t st = sb + (c & 1) * kStageBytes;
#pragma unroll
        for (int kk = 0; kk < 4; kk++) {          // four k16 steps per chunk
            const uint32_t kOff = kk * 32;
            uint32_t ah[2][4], b[8][2];
#pragma unroll
            for (int mt = 0; mt < 2; mt++)
                ldsm_x4(ah[mt], st + OFF_A + aRowOff + mt * 16 * kRowBytes + kOff);
#pragma unroll
            for (int np = 0; np < 4; np++)
                ldsm_x4(&b[np * 2][0], st + OFF_BH + bRowOff + np * 16 * kRowBytes + kOff);
#pragma unroll
            for (int mt = 0; mt < 2; mt++)
#pragma unroll
                for (int nt = 0; nt < 8; nt++)
                    mma16816(acc[mt][nt], ah[mt], b[nt]);
            if (SPLIT) {
#pragma unroll
                for (int np = 0; np < 4; np++)
                    ldsm_x4(&b[np * 2][0], st + OFF_BL + bRowOff + np * 16 * kRowBytes + kOff);
#pragma unroll
                for (int mt = 0; mt < 2; mt++)
#pragma unroll
                    for (int nt = 0; nt < 8; nt++)
                        mma16816(acc[mt][nt], ah[mt], b[nt]);
            }
        }
        __syncthreads();
    }

    const int mBase = m0 + wm * 32;
    const int nBase = n0 + wn * 64;
#pragma unroll
    for (int mt = 0; mt < 2; mt++) {
#pragma unroll
        for (int nt = 0; nt < 8; nt++) {
            float* a4 = acc[mt][nt];
            if (epi_sigmoid) {
#pragma unroll
                for (int i = 0; i < 4; i++)
                    a4[i] = 1.f / (1.f + __expf(-a4[i]));
            }
            const int r0 = mBase + mt * 16 + (lane >> 2);
            const int cc = nBase + nt * 8 + (lane & 3) * 2;
            *(float2*)(out + (size_t)r0 * kC + cc)       = make_float2(a4[0], a4[1]);
            *(float2*)(out + (size_t)(r0 + 8) * kC + cc) = make_float2(a4[2], a4[3]);
        }
    }
}

// merged k/v/r GEMM: z=0 -> key (split), z=1 -> value, z=2 -> sigmoid(recept.)
__global__ __launch_bounds__(256, 2) void gemm_kvr_kernel() {
    const int z = blockIdx.z;
    if (z == 0)      gemm_body<true >(g_a[0], g_wh[0], g_wkl,  g_kvr[0], 0);
    else if (z == 1) gemm_body<false>(g_a[1], g_wh[1], nullptr, g_kvr[1], 0);
    else             gemm_body<false>(g_a[2], g_wh[2], nullptr, g_kvr[2], 1);
}
__global__ __launch_bounds__(256, 2) void gemm_out_kernel(float* __restrict__ out) {
    gemm_body<true>(g_rw, g_woh, g_wol, out, 0);
}

// ---------------------------------------------------------------------------
// WKV blocked scan.
// ---------------------------------------------------------------------------
__global__ void wkv_segA(const float* __restrict__ td) {
    const int c  = blockIdx.x * blockDim.x + threadIdx.x;
    const int bs = blockIdx.y;
    const int b  = bs >> 4;
    const int sg = bs & (kSeg - 1);

    const float w = -__expf(td[c]);
    const size_t base = ((size_t)b * kT + (size_t)sg * kSegLen) * kC + c;
    const float* kp = g_kvr[0] + base;
    const float* vp = g_kvr[1] + base;

    float num = 0.f, den = 0.f, mx = -1e38f;
#pragma unroll 4
    for (int i = 0; i < kSegLen; i++) {
        const float k = kp[(size_t)i * kC];
        const float v = vp[(size_t)i * kC];
        const float mw = mx + w;
        const float ms = fmaxf(mw, k);
        const float e1 = __expf(mw - ms);
        const float e2 = __expf(k - ms);
        num = fmaf(e1, num, e2 * v);
        den = fmaf(e1, den, e2);
        mx = ms;
    }
    const size_t si = (size_t)bs * kC + c;
    g_segN[si] = num;
    g_segD[si] = den;
    g_segM[si] = mx;
}

__global__ void wkv_prefix(const float* __restrict__ td) {
    const int idx = blockIdx.x * blockDim.x + threadIdx.x;
    const int b = idx >> 10;
    const int c = idx & (kC - 1);
    const float w = -__expf(td[c]);
    const float shift = (float)kSegLen * w;

    float N = 0.f, D = 0.f, M = -1e38f;
#pragma unroll
    for (int s = 0; s < kSeg; s++) {
        const size_t si = ((size_t)(b * kSeg + s)) * kC + c;
        const float n = g_segN[si];
        const float d = g_segD[si];
        const float m = g_segM[si];
        g_segN[si] = N;
        g_segD[si] = D;
        g_segM[si] = M;
        const float Ms = M + shift;
        const float nm = fmaxf(Ms, m);
        const float ea = __expf(Ms - nm);
        const float eb = __expf(m - nm);
        N = fmaf(ea, N, eb * n);
        D = fmaf(ea, D, eb * d);
        M = nm;
    }
}

__global__ void wkv_segB(const float* __restrict__ td, const float* __restrict__ tf) {
    const int c  = blockIdx.x * blockDim.x + threadIdx.x;
    const int bs = blockIdx.y;
    const int b  = bs >> 4;
    const int sg = bs & (kSeg - 1);

    const float w = -__expf(td[c]);
    const float u = tf[c];

    const size_t si = (size_t)bs * kC + c;
    float num = g_segN[si];
    float den = g_segD[si];
    float mx  = g_segM[si];

    const size_t base = ((size_t)b * kT + (size_t)sg * kSegLen) * kC + c;
    const float* kp = g_kvr[0] + base;
    const float* vp = g_kvr[1] + base;
    const float* rp = g_kvr[2] + base;
    __half* op = g_rw + base;

#pragma unroll 4
    for (int i = 0; i < kSegLen; i++) {
        const size_t o = (size_t)i * kC;
        const float k = kp[o];
        const float v = vp[o];
        const float r = rp[o];
        const float ku = k + u;
        const float mo = fmaxf(mx, ku);
        const float e1 = __expf(mx - mo);
        const float e2 = __expf(ku - mo);
        const float outv = __fdividef(fmaf(e1, num, e2 * v), fmaf(e1, den, e2));
        const float mw = mx + w;
        const float ms = fmaxf(mw, k);
        const float e1s = __expf(mw - ms);
        const float e2s = __expf(k - ms);
        num = fmaf(e1s, num, e2s * v);
        den = fmaf(e1s, den, e2s);
        mx = ms;

        op[o] = __float2half_rn(r * outv);
    }
}

// ---------------------------------------------------------------------------
// Launch
// ---------------------------------------------------------------------------
extern "C" void kernel_launch(void* const* d_in, const int* in_sizes, int n_in,
                              void* d_out, int out_size) {
    const float* x  = (const float*)d_in[0];
    const float* wk = (const float*)d_in[1];
    const float* wv = (const float*)d_in[2];
    const float* wr = (const float*)d_in[3];
    const float* wo = (const float*)d_in[4];
    const float* td = (const float*)d_in[5];
    const float* tf = (const float*)d_in[6];
    const float* mk = (const float*)d_in[7];
    const float* mv = (const float*)d_in[8];
    const float* mr = (const float*)d_in[9];
    float* out = (float*)d_out;

    cudaFuncSetAttribute(gemm_kvr_kernel, cudaFuncAttributeMaxDynamicSharedMemorySize, kSmemBytes);
    cudaFuncSetAttribute(gemm_out_kernel, cudaFuncAttributeMaxDynamicSharedMemorySize, kSmemBytes);

    prep_w_kernel<<<dim3(kC, 4), 256>>>(wk, wv, wr, wo);
    prep_a_kernel<<<kM, 256>>>(x, mk, mv, mr);

    gemm_kvr_kernel<<<dim3(kC / 128, kM / 128, 3), 256, kSmemBytes>>>();

    dim3 wgrid(kC / 256, kB * kSeg);   // (4, 128)
    wkv_segA<<<wgrid, 256>>>(td);
    wkv_prefix<<<(kB * kC) / 256, 256>>>(td);
    wkv_segB<<<wgrid, 256>>>(td, tf);

    gemm_out_kernel<<<dim3(kC / 128, kM / 128), 256, kSmemBytes>>>(out);
}

// round 9
// speedup vs baseline: 1.4043x; 1.4043x over previous
#include <cuda_runtime.h>
#include <cuda_fp16.h>
#include <cstdint>
#include <math.h>

// Problem shape (fixed): B=8, T=2048, C=1024
constexpr int kB = 8;
constexpr int kT = 2048;
constexpr int kC = 1024;
constexpr int kM = kB * kT;                 // 16384 rows
constexpr size_t kMC = (size_t)kM * kC;
constexpr size_t kCC = (size_t)kC * kC;

// WKV blocked-scan config
constexpr int kSeg    = 16;
constexpr int kSegLen = kT / kSeg;          // 128

// ---------------------------------------------------------------------------
// Scratch (__device__ globals; no allocations allowed)
// ---------------------------------------------------------------------------
__device__ __half g_a[3][kMC];     // mixed inputs (k,v,r) in fp16
__device__ __half g_w[4][kCC];     // wk,wv,wr,wo in fp16
__device__ float  g_kvr[3][kMC];   // key, value, sigmoid(r)
__device__ __half g_rw[kMC];       // rwkv in fp16
__device__ float g_segN[(size_t)kB * kSeg * kC];
__device__ float g_segD[(size_t)kB * kSeg * kC];
__device__ float g_segM[(size_t)kB * kSeg * kC];

// ---------------------------------------------------------------------------
// PTX helpers
// ---------------------------------------------------------------------------
__device__ __forceinline__ uint32_t smem_u32(const void* p) {
    uint32_t a;
    asm("{ .reg .u64 t; cvta.to.shared.u64 t, %1; cvt.u32.u64 %0, t; }"
        : "=r"(a) : "l"(p));
    return a;
}
__device__ __forceinline__ void cp_async16(uint32_t saddr, const void* gptr) {
    asm volatile("cp.async.ca.shared.global [%0], [%1], 16;"
                 :: "r"(saddr), "l"(gptr));
}
__device__ __forceinline__ void cp_commit() {
    asm volatile("cp.async.commit_group;");
}
template <int N>
__device__ __forceinline__ void cp_wait() {
    asm volatile("cp.async.wait_group %0;" :: "n"(N));
}
__device__ __forceinline__ void ldsm_x4(uint32_t* r, uint32_t addr) {
    asm volatile("ldmatrix.sync.aligned.m8n8.x4.shared.b16 {%0,%1,%2,%3}, [%4];"
                 : "=r"(r[0]), "=r"(r[1]), "=r"(r[2]), "=r"(r[3]) : "r"(addr));
}
__device__ __forceinline__ void mma16816(float* d, const uint32_t* a, const uint32_t* b) {
    asm volatile("mma.sync.aligned.m16n8k16.row.col.f32.f16.f16.f32 "
                 "{%0,%1,%2,%3}, {%4,%5,%6,%7}, {%8,%9}, {%0,%1,%2,%3};"
                 : "+f"(d[0]), "+f"(d[1]), "+f"(d[2]), "+f"(d[3])
                 : "r"(a[0]), "r"(a[1]), "r"(a[2]), "r"(a[3]), "r"(b[0]), "r"(b[1]));
}

// ---------------------------------------------------------------------------
// fp16 helpers
// ---------------------------------------------------------------------------
__device__ __forceinline__ void h4_store(const float* a, __half* d, size_t off) {
    unsigned short u[4];
#pragma unroll
    for (int i = 0; i < 4; i++) u[i] = __half_as_ushort(__float2half_rn(a[i]));
    *(uint2*)(d + off) = make_uint2((uint32_t)u[0] | ((uint32_t)u[1] << 16),
                                    (uint32_t)u[2] | ((uint32_t)u[3] << 16));
}

// ---------------------------------------------------------------------------
// prep kernels
// ---------------------------------------------------------------------------
__global__ void prep_w_kernel(const float* __restrict__ wk, const float* __restrict__ wv,
                              const float* __restrict__ wr, const float* __restrict__ wo) {
    const int mat = blockIdx.y;
    const int row = blockIdx.x;
    const int c4  = threadIdx.x;
    const float* src = mat == 0 ? wk : mat == 1 ? wv : mat == 2 ? wr : wo;
    const size_t off = (size_t)row * kC + c4 * 4;
    float4 v = ((const float4*)(src + (size_t)row * kC))[c4];
    h4_store((const float*)&v, g_w[mat], off);
}

__global__ void prep_a_kernel(const float* __restrict__ x,
                              const float* __restrict__ mk,
                              const float* __restrict__ mv,
                              const float* __restrict__ mr) {
    const int row = blockIdx.x;
    const int c4  = threadIdx.x;
    const float4 xv = ((const float4*)(x + (size_t)row * kC))[c4];
    float4 pv = make_float4(0.f, 0.f, 0.f, 0.f);
    if ((row & (kT - 1)) != 0)
        pv = ((const float4*)(x + (size_t)(row - 1) * kC))[c4];
    const float4 m0 = ((const float4*)mk)[c4];
    const float4 m1 = ((const float4*)mv)[c4];
    const float4 m2 = ((const float4*)mr)[c4];
    const float* xe = (const float*)&xv;
    const float* pe = (const float*)&pv;
    const float* me[3] = {(const float*)&m0, (const float*)&m1, (const float*)&m2};
    const size_t off = (size_t)row * kC + c4 * 4;
#pragma unroll
    for (int s = 0; s < 3; s++) {
        float a[4];
#pragma unroll
        for (int i = 0; i < 4; i++)
            a[i] = fmaf(me[s][i], xe[i] - pe[i], pe[i]);
        h4_store(a, g_a[s], off);
    }
}

// ---------------------------------------------------------------------------
// fp16 warp-MMA GEMM: out[m,n] = sum_k A[m,k]*B[n,k]
// CTA tile 128x128, K-chunk 64, 8 warps (warp tile 32x64), cp.async dbl-buffer
// ---------------------------------------------------------------------------
constexpr int kStrideB16 = 72;               // padded smem row stride (b16)
constexpr int kRowBytes  = kStrideB16 * 2;   // 144
constexpr int kTileBytes = 128 * kRowBytes;  // 18432
constexpr int kStageBytes = 2 * kTileBytes;  // 36864 (A, B)
constexpr int kSmemBytes  = 2 * kStageBytes; // 73728
constexpr int OFF_A = 0;
constexpr int OFF_B = kTileBytes;

__device__ __forceinline__ void load_chunk(uint32_t sb, int stage, int tid,
                                           const __half* A, const __half* B,
                                           int m0, int n0, int k0) {
    const uint32_t st = sb + stage * kStageBytes;
    const __half* srcs[2] = {A, B};
    const int bases[2] = {m0, n0};
    const uint32_t offs[2] = {OFF_A, OFF_B};
#pragma unroll
    for (int t = 0; t < 2; t++) {
#pragma unroll
        for (int rep = 0; rep < 4; rep++) {
            const int j = tid + rep * 256;         // 0..1023
            const int row = j >> 3;
            const int seg = j & 7;
            const __half* g = srcs[t] + (size_t)(bases[t] + row) * kC + k0 + seg * 8;
            cp_async16(st + offs[t] + row * kRowBytes + seg * 16, g);
        }
    }
}

__device__ __forceinline__ void gemm_body(const __half* __restrict__ A,
                                          const __half* __restrict__ B,
                                          float* __restrict__ out,
                                          int epi_sigmoid) {
    extern __shared__ char smem[];
    const uint32_t sb = smem_u32(smem);
    const int tid  = threadIdx.x;
    const int wid  = tid >> 5;
    const int lane = tid & 31;
    const int wm   = wid & 3;
    const int wn   = wid >> 2;

    const int m0 = blockIdx.y * 128;
    const int n0 = blockIdx.x * 128;

    float acc[2][8][4];
#pragma unroll
    for (int mt = 0; mt < 2; mt++)
#pragma unroll
        for (int nt = 0; nt < 8; nt++)
#pragma unroll
            for (int i = 0; i < 4; i++) acc[mt][nt][i] = 0.f;

    const uint32_t aRowOff = (uint32_t)((wm * 32 + (lane & 15)) * kRowBytes + (lane >> 4) * 16);
    const uint32_t bRowOff = (uint32_t)((wn * 64 + (lane & 7) + ((lane & 16) >> 1)) * kRowBytes
                                        + ((lane >> 3) & 1) * 16);

    load_chunk(sb, 0, tid, A, B, m0, n0, 0);
    cp_commit();

    const int nChunks = kC / 64;   // 16
    for (int c = 0; c < nChunks; c++) {
        if (c + 1 < nChunks) {
            load_chunk(sb, (c + 1) & 1, tid, A, B, m0, n0, (c + 1) * 64);
            cp_commit();
            cp_wait<1>();
        } else {
            cp_wait<0>();
        }
        __syncthreads();

        const uint32_t st = sb + (c & 1) * kStageBytes;
#pragma unroll
        for (int kk = 0; kk < 4; kk++) {          // four k16 steps per chunk
            const uint32_t kOff = kk * 32;
            uint32_t ah[2][4], b[8][2];
#pragma unroll
            for (int mt = 0; mt < 2; mt++)
                ldsm_x4(ah[mt], st + OFF_A + aRowOff + mt * 16 * kRowBytes + kOff);
#pragma unroll
            for (int np = 0; np < 4; np++)
                ldsm_x4(&b[np * 2][0], st + OFF_B + bRowOff + np * 16 * kRowBytes + kOff);
#pragma unroll
            for (int mt = 0; mt < 2; mt++)
#pragma unroll
                for (int nt = 0; nt < 8; nt++)
                    mma16816(acc[mt][nt], ah[mt], b[nt]);
        }
        __syncthreads();
    }

    const int mBase = m0 + wm * 32;
    const int nBase = n0 + wn * 64;
#pragma unroll
    for (int mt = 0; mt < 2; mt++) {
#pragma unroll
        for (int nt = 0; nt < 8; nt++) {
            float* a4 = acc[mt][nt];
            if (epi_sigmoid) {
#pragma unroll
                for (int i = 0; i < 4; i++)
                    a4[i] = 1.f / (1.f + __expf(-a4[i]));
            }
            const int r0 = mBase + mt * 16 + (lane >> 2);
            const int cc = nBase + nt * 8 + (lane & 3) * 2;
            *(float2*)(out + (size_t)r0 * kC + cc)       = make_float2(a4[0], a4[1]);
            *(float2*)(out + (size_t)(r0 + 8) * kC + cc) = make_float2(a4[2], a4[3]);
        }
    }
}

// merged k/v/r GEMM: z=0 -> key, z=1 -> value, z=2 -> sigmoid(receptance)
__global__ __launch_bounds__(256, 2) void gemm_kvr_kernel() {
    const int z = blockIdx.z;
    gemm_body(g_a[z], g_w[z], g_kvr[z], z == 2 ? 1 : 0);
}
__global__ __launch_bounds__(256, 2) void gemm_out_kernel(float* __restrict__ out) {
    gemm_body(g_rw, g_w[3], out, 0);
}

// ---------------------------------------------------------------------------
// WKV blocked scan.
// ---------------------------------------------------------------------------
__global__ void wkv_segA(const float* __restrict__ td) {
    const int c  = blockIdx.x * blockDim.x + threadIdx.x;
    const int bs = blockIdx.y;
    const int b  = bs >> 4;
    const int sg = bs & (kSeg - 1);

    const float w = -__expf(td[c]);
    const size_t base = ((size_t)b * kT + (size_t)sg * kSegLen) * kC + c;
    const float* kp = g_kvr[0] + base;
    const float* vp = g_kvr[1] + base;

    float num = 0.f, den = 0.f, mx = -1e38f;
#pragma unroll 4
    for (int i = 0; i < kSegLen; i++) {
        const float k = kp[(size_t)i * kC];
        const float v = vp[(size_t)i * kC];
        const float mw = mx + w;
        const float ms = fmaxf(mw, k);
        const float e1 = __expf(mw - ms);
        const float e2 = __expf(k - ms);
        num = fmaf(e1, num, e2 * v);
        den = fmaf(e1, den, e2);
        mx = ms;
    }
    const size_t si = (size_t)bs * kC + c;
    g_segN[si] = num;
    g_segD[si] = den;
    g_segM[si] = mx;
}

__global__ void wkv_prefix(const float* __restrict__ td) {
    const int idx = blockIdx.x * blockDim.x + threadIdx.x;
    const int b = idx >> 10;
    const int c = idx & (kC - 1);
    const float w = -__expf(td[c]);
    const float shift = (float)kSegLen * w;

    float N = 0.f, D = 0.f, M = -1e38f;
#pragma unroll
    for (int s = 0; s < kSeg; s++) {
        const size_t si = ((size_t)(b * kSeg + s)) * kC + c;
        const float n = g_segN[si];
        const float d = g_segD[si];
        const float m = g_segM[si];
        g_segN[si] = N;
        g_segD[si] = D;
        g_segM[si] = M;
        const float Ms = M + shift;
        const float nm = fmaxf(Ms, m);
        const float ea = __expf(Ms - nm);
        const float eb = __expf(m - nm);
        N = fmaf(ea, N, eb * n);
        D = fmaf(ea, D, eb * d);
        M = nm;
    }
}

__global__ void wkv_segB(const float* __restrict__ td, const float* __restrict__ tf) {
    const int c  = blockIdx.x * blockDim.x + threadIdx.x;
    const int bs = blockIdx.y;
    const int b  = bs >> 4;
    const int sg = bs & (kSeg - 1);

    const float w = -__expf(td[c]);
    const float u = tf[c];

    const size_t si = (size_t)bs * kC + c;
    float num = g_segN[si];
    float den = g_segD[si];
    float mx  = g_segM[si];

    const size_t base = ((size_t)b * kT + (size_t)sg * kSegLen) * kC + c;
    const float* kp = g_kvr[0] + base;
    const float* vp = g_kvr[1] + base;
    const float* rp = g_kvr[2] + base;
    __half* op = g_rw + base;

#pragma unroll 4
    for (int i = 0; i < kSegLen; i++) {
        const size_t o = (size_t)i * kC;
        const float k = kp[o];
        const float v = vp[o];
        const float r = rp[o];
        const float ku = k + u;
        const float mo = fmaxf(mx, ku);
        const float e1 = __expf(mx - mo);
        const float e2 = __expf(ku - mo);
        const float outv = __fdividef(fmaf(e1, num, e2 * v), fmaf(e1, den, e2));
        const float mw = mx + w;
        const float ms = fmaxf(mw, k);
        const float e1s = __expf(mw - ms);
        const float e2s = __expf(k - ms);
        num = fmaf(e1s, num, e2s * v);
        den = fmaf(e1s, den, e2s);
        mx = ms;

        op[o] = __float2half_rn(r * outv);
    }
}

// ---------------------------------------------------------------------------
// Launch
// ---------------------------------------------------------------------------
extern "C" void kernel_launch(void* const* d_in, const int* in_sizes, int n_in,
                              void* d_out, int out_size) {
    const float* x  = (const float*)d_in[0];
    const float* wk = (const float*)d_in[1];
    const float* wv = (const float*)d_in[2];
    const float* wr = (const float*)d_in[3];
    const float* wo = (const float*)d_in[4];
    const float* td = (const float*)d_in[5];
    const float* tf = (const float*)d_in[6];
    const float* mk = (const float*)d_in[7];
    const float* mv = (const float*)d_in[8];
    const float* mr = (const float*)d_in[9];
    float* out = (float*)d_out;

    cudaFuncSetAttribute(gemm_kvr_kernel, cudaFuncAttributeMaxDynamicSharedMemorySize, kSmemBytes);
    cudaFuncSetAttribute(gemm_out_kernel, cudaFuncAttributeMaxDynamicSharedMemorySize, kSmemBytes);

    prep_w_kernel<<<dim3(kC, 4), 256>>>(wk, wv, wr, wo);
    prep_a_kernel<<<kM, 256>>>(x, mk, mv, mr);

    gemm_kvr_kernel<<<dim3(kC / 128, kM / 128, 3), 256, kSmemBytes>>>();

    dim3 wgrid(kC / 256, kB * kSeg);   // (4, 128)
    wkv_segA<<<wgrid, 256>>>(td);
    wkv_prefix<<<(kB * kC) / 256, 256>>>(td);
    wkv_segB<<<wgrid, 256>>>(td, tf);

    gemm_out_kernel<<<dim3(kC / 128, kM / 128), 256, kSmemBytes>>>(out);
}